// round 2
// baseline (speedup 1.0000x reference)
#include <cuda_runtime.h>

#define B_TOTAL 262144
#define IN_DIM 28
#define HID 128
#define LAT 64
#define NCODES 512

#define GRID1 148
#define WARPS1 12
#define THREADS1 (WARPS1 * 32)
#define ROWB 4
#define TOTWARPS (GRID1 * WARPS1)

// ---- K1 shared-memory layout (floats) ----
#define OF_W1   0
#define OF_B1   (OF_W1 + IN_DIM * HID)        // 3584
#define OF_W2   (OF_B1 + HID)                 // 3712
#define OF_B2   (OF_W2 + HID * LAT)           // 11904
#define OF_CBT  (OF_B2 + LAT)                 // 11968  (k-major codebook [k*512+c])
#define OF_E2   (OF_CBT + LAT * NCODES)       // 44736
#define OF_SCR1 (OF_E2 + NCODES)              // 45248
#define WSCR1   (ROWB * IN_DIM + ROWB * HID + ROWB * LAT)  // 880 per warp
#define SMEM1_FLOATS (OF_SCR1 + WARPS1 * WSCR1)
#define SMEM1_BYTES  (SMEM1_FLOATS * 4)

// ---- K2 shared-memory layout (floats) ----
#define OF_DW1  0
#define OF_DB1  (OF_DW1 + LAT * HID)          // 8192
#define OF_DW2  (OF_DB1 + HID)                // 8320
#define OF_DB2  (OF_DW2 + HID * IN_DIM)       // 11904
#define OF_CB2  (OF_DB2 + IN_DIM)             // 11932 (row-major codebook)
#define OF_SCR2 (OF_CB2 + NCODES * LAT)       // 44700
#define WSCR2   (ROWB * LAT + ROWB * HID)     // 768 per warp
#define SMEM2_FLOATS (OF_SCR2 + WARPS1 * WSCR2)
#define SMEM2_BYTES  (SMEM2_FLOATS * 4)

__device__ int   g_idx[B_TOTAL];
__device__ float g_vq_part[GRID1];
__device__ float g_rec_part[GRID1];

// ============================================================================
// K1: encoder (x -> h -> z), nearest-code argmin, vq-loss partials
// ============================================================================
__global__ void __launch_bounds__(THREADS1, 1)
k_encode(const float* __restrict__ x,
         const float* __restrict__ w1, const float* __restrict__ b1,
         const float* __restrict__ w2, const float* __restrict__ b2,
         const float* __restrict__ cb)
{
    extern __shared__ float sm[];
    float* s_w1  = sm + OF_W1;
    float* s_b1  = sm + OF_B1;
    float* s_w2  = sm + OF_W2;
    float* s_b2  = sm + OF_B2;
    float* s_cbt = sm + OF_CBT;
    float* s_e2  = sm + OF_E2;

    const int tid = threadIdx.x;

    for (int i = tid; i < IN_DIM * HID; i += THREADS1) s_w1[i] = w1[i];
    for (int i = tid; i < HID;          i += THREADS1) s_b1[i] = b1[i];
    for (int i = tid; i < HID * LAT;    i += THREADS1) s_w2[i] = w2[i];
    for (int i = tid; i < LAT;          i += THREADS1) s_b2[i] = b2[i];
    // codebook transposed to k-major for conflict-free distance loop
    for (int i = tid; i < NCODES * LAT; i += THREADS1) {
        int c = i / LAT, k = i % LAT;
        s_cbt[k * NCODES + c] = cb[i];
    }
    for (int c = tid; c < NCODES; c += THREADS1) {
        float s = 0.f;
        for (int k = 0; k < LAT; k++) { float v = cb[c * LAT + k]; s = fmaf(v, v, s); }
        s_e2[c] = s;
    }
    __syncthreads();

    const int warp = tid >> 5, lane = tid & 31;
    float* xs = sm + OF_SCR1 + warp * WSCR1;     // [ROWB][28]
    float* hs = xs + ROWB * IN_DIM;              // [ROWB][128]
    float* zs = hs + ROWB * HID;                 // [ROWB][64]

    const unsigned FULL = 0xffffffffu;
    float vq_local = 0.f;
    const int gw = blockIdx.x * WARPS1 + warp;

    for (int base = gw * ROWB; base < B_TOTAL; base += TOTWARPS * ROWB) {
        // --- load x tile ---
        const float* xg = x + (long)base * IN_DIM;
        for (int i = lane; i < ROWB * IN_DIM; i += 32) xs[i] = xg[i];
        __syncwarp();

        // --- phase B: h = relu(x @ W1 + b1) ---
        {
            float acc[ROWB][4];
            #pragma unroll
            for (int r = 0; r < ROWB; r++)
                #pragma unroll
                for (int jj = 0; jj < 4; jj++) acc[r][jj] = s_b1[lane + 32 * jj];
            #pragma unroll 4
            for (int k = 0; k < IN_DIM; k++) {
                float wv[4];
                #pragma unroll
                for (int jj = 0; jj < 4; jj++) wv[jj] = s_w1[k * HID + lane + 32 * jj];
                #pragma unroll
                for (int r = 0; r < ROWB; r++) {
                    float xv = xs[r * IN_DIM + k];
                    #pragma unroll
                    for (int jj = 0; jj < 4; jj++) acc[r][jj] = fmaf(xv, wv[jj], acc[r][jj]);
                }
            }
            #pragma unroll
            for (int r = 0; r < ROWB; r++)
                #pragma unroll
                for (int jj = 0; jj < 4; jj++)
                    hs[r * HID + lane + 32 * jj] = fmaxf(acc[r][jj], 0.f);
        }
        __syncwarp();

        // --- phase C: z = h @ W2 + b2 ---
        {
            float acc[ROWB][2];
            #pragma unroll
            for (int r = 0; r < ROWB; r++) {
                acc[r][0] = s_b2[lane];
                acc[r][1] = s_b2[lane + 32];
            }
            #pragma unroll 4
            for (int k = 0; k < HID; k++) {
                float w0 = s_w2[k * LAT + lane];
                float w1v = s_w2[k * LAT + lane + 32];
                #pragma unroll
                for (int r = 0; r < ROWB; r++) {
                    float hv = hs[r * HID + k];
                    acc[r][0] = fmaf(hv, w0,  acc[r][0]);
                    acc[r][1] = fmaf(hv, w1v, acc[r][1]);
                }
            }
            #pragma unroll
            for (int r = 0; r < ROWB; r++) {
                zs[r * LAT + lane]      = acc[r][0];
                zs[r * LAT + lane + 32] = acc[r][1];
            }
        }
        __syncwarp();

        // --- phase D: distances + argmin (||e||^2 - 2 z.e; ||z||^2 is row-const) ---
        float minv[ROWB];
        int   mini[ROWB];
        #pragma unroll
        for (int r = 0; r < ROWB; r++) { minv[r] = 3.4e38f; mini[r] = 0; }

        #pragma unroll
        for (int cc = 0; cc < 4; cc++) {
            float dacc[ROWB][4];
            #pragma unroll
            for (int r = 0; r < ROWB; r++)
                #pragma unroll
                for (int u = 0; u < 4; u++) dacc[r][u] = 0.f;
            const int c0 = lane + 128 * cc;
            #pragma unroll 4
            for (int k = 0; k < LAT; k++) {
                float cv[4];
                #pragma unroll
                for (int u = 0; u < 4; u++) cv[u] = s_cbt[k * NCODES + c0 + 32 * u];
                #pragma unroll
                for (int r = 0; r < ROWB; r++) {
                    float zv = zs[r * LAT + k];
                    #pragma unroll
                    for (int u = 0; u < 4; u++) dacc[r][u] = fmaf(zv, cv[u], dacc[r][u]);
                }
            }
            #pragma unroll
            for (int u = 0; u < 4; u++) {
                int c = c0 + 32 * u;
                float e = s_e2[c];
                #pragma unroll
                for (int r = 0; r < ROWB; r++) {
                    float d = fmaf(-2.f, dacc[r][u], e);
                    if (d < minv[r]) { minv[r] = d; mini[r] = c; }
                }
            }
        }

        // warp argmin reduce (first-occurrence tie-break: smaller index)
        #pragma unroll
        for (int r = 0; r < ROWB; r++) {
            float mv = minv[r]; int mi = mini[r];
            #pragma unroll
            for (int off = 16; off; off >>= 1) {
                float ov = __shfl_down_sync(FULL, mv, off);
                int   oi = __shfl_down_sync(FULL, mi, off);
                if (ov < mv || (ov == mv && oi < mi)) { mv = ov; mi = oi; }
            }
            mini[r] = __shfl_sync(FULL, mi, 0);
        }
        if (lane == 0) {
            #pragma unroll
            for (int r = 0; r < ROWB; r++) g_idx[base + r] = mini[r];
        }

        // vq loss partial: sum (z - q)^2
        #pragma unroll
        for (int r = 0; r < ROWB; r++) {
            int mi = mini[r];
            #pragma unroll
            for (int jj = 0; jj < 2; jj++) {
                int k = lane + 32 * jj;
                float d = zs[r * LAT + k] - s_cbt[k * NCODES + mi];
                vq_local = fmaf(d, d, vq_local);
            }
        }
    }

    // block reduce vq_local
    #pragma unroll
    for (int off = 16; off; off >>= 1) vq_local += __shfl_down_sync(FULL, vq_local, off);
    __syncthreads();              // weights no longer needed; reuse smem
    if (lane == 0) sm[warp] = vq_local;
    __syncthreads();
    if (tid == 0) {
        float s = 0.f;
        for (int w = 0; w < WARPS1; w++) s += sm[w];
        g_vq_part[blockIdx.x] = s;
    }
}

// ============================================================================
// K2: decoder (q -> hd -> recon), recon write + recon-loss partials
// ============================================================================
__global__ void __launch_bounds__(THREADS1, 1)
k_decode(const float* __restrict__ x, const float* __restrict__ cb,
         const float* __restrict__ dw1, const float* __restrict__ db1,
         const float* __restrict__ dw2, const float* __restrict__ db2,
         float* __restrict__ out)
{
    extern __shared__ float sm[];
    float* s_w1 = sm + OF_DW1;
    float* s_b1 = sm + OF_DB1;
    float* s_w2 = sm + OF_DW2;
    float* s_b2 = sm + OF_DB2;
    float* s_cb = sm + OF_CB2;

    const int tid = threadIdx.x;
    for (int i = tid; i < LAT * HID;    i += THREADS1) s_w1[i] = dw1[i];
    for (int i = tid; i < HID;          i += THREADS1) s_b1[i] = db1[i];
    for (int i = tid; i < HID * IN_DIM; i += THREADS1) s_w2[i] = dw2[i];
    for (int i = tid; i < IN_DIM;       i += THREADS1) s_b2[i] = db2[i];
    for (int i = tid; i < NCODES * LAT; i += THREADS1) s_cb[i] = cb[i];
    __syncthreads();

    const int warp = tid >> 5, lane = tid & 31;
    float* qs  = sm + OF_SCR2 + warp * WSCR2;   // [ROWB][64]
    float* hds = qs + ROWB * LAT;               // [ROWB][128]

    const unsigned FULL = 0xffffffffu;
    float rec_local = 0.f;
    const int gw = blockIdx.x * WARPS1 + warp;

    for (int base = gw * ROWB; base < B_TOTAL; base += TOTWARPS * ROWB) {
        // --- gather quantized rows ---
        int idx4[ROWB];
        #pragma unroll
        for (int r = 0; r < ROWB; r++) idx4[r] = g_idx[base + r];
        #pragma unroll
        for (int r = 0; r < ROWB; r++) {
            qs[r * LAT + lane]      = s_cb[idx4[r] * LAT + lane];
            qs[r * LAT + lane + 32] = s_cb[idx4[r] * LAT + lane + 32];
        }
        __syncwarp();

        // --- hd = relu(q @ dW1 + db1) ---
        {
            float acc[ROWB][4];
            #pragma unroll
            for (int r = 0; r < ROWB; r++)
                #pragma unroll
                for (int jj = 0; jj < 4; jj++) acc[r][jj] = s_b1[lane + 32 * jj];
            #pragma unroll 4
            for (int k = 0; k < LAT; k++) {
                float wv[4];
                #pragma unroll
                for (int jj = 0; jj < 4; jj++) wv[jj] = s_w1[k * HID + lane + 32 * jj];
                #pragma unroll
                for (int r = 0; r < ROWB; r++) {
                    float qv = qs[r * LAT + k];
                    #pragma unroll
                    for (int jj = 0; jj < 4; jj++) acc[r][jj] = fmaf(qv, wv[jj], acc[r][jj]);
                }
            }
            #pragma unroll
            for (int r = 0; r < ROWB; r++)
                #pragma unroll
                for (int jj = 0; jj < 4; jj++)
                    hds[r * HID + lane + 32 * jj] = fmaxf(acc[r][jj], 0.f);
        }
        __syncwarp();

        // --- recon = hd @ dW2 + db2, write + loss ---
        if (lane < IN_DIM) {
            float acc[ROWB];
            #pragma unroll
            for (int r = 0; r < ROWB; r++) acc[r] = s_b2[lane];
            #pragma unroll 4
            for (int k = 0; k < HID; k++) {
                float wv = s_w2[k * IN_DIM + lane];
                #pragma unroll
                for (int r = 0; r < ROWB; r++) acc[r] = fmaf(hds[r * HID + k], wv, acc[r]);
            }
            #pragma unroll
            for (int r = 0; r < ROWB; r++) {
                long o = (long)(base + r) * IN_DIM + lane;
                out[o] = acc[r];
                float d = acc[r] - x[o];
                rec_local = fmaf(d, d, rec_local);
            }
        }
    }

    #pragma unroll
    for (int off = 16; off; off >>= 1) rec_local += __shfl_down_sync(FULL, rec_local, off);
    __syncthreads();
    if (lane == 0) sm[warp] = rec_local;
    __syncthreads();
    if (tid == 0) {
        float s = 0.f;
        for (int w = 0; w < WARPS1; w++) s += sm[w];
        g_rec_part[blockIdx.x] = s;
    }
}

// ============================================================================
// K3: finalize scalar losses
// ============================================================================
__global__ void k_final(float* __restrict__ out)
{
    if (threadIdx.x == 0) {
        double vs = 0.0, rs = 0.0;
        for (int i = 0; i < GRID1; i++) { vs += (double)g_vq_part[i]; rs += (double)g_rec_part[i]; }
        out[(long)B_TOTAL * IN_DIM]     = (float)(rs / ((double)B_TOTAL * IN_DIM));
        out[(long)B_TOTAL * IN_DIM + 1] = (float)(1.25 * vs / ((double)B_TOTAL * LAT));
    }
}

// ============================================================================
extern "C" void kernel_launch(void* const* d_in, const int* in_sizes, int n_in,
                              void* d_out, int out_size)
{
    const float* x    = (const float*)d_in[0];
    const float* ew1  = (const float*)d_in[1];
    const float* eb1  = (const float*)d_in[2];
    const float* ew2  = (const float*)d_in[3];
    const float* eb2  = (const float*)d_in[4];
    const float* cb   = (const float*)d_in[5];
    const float* dw1  = (const float*)d_in[6];
    const float* db1  = (const float*)d_in[7];
    const float* dw2  = (const float*)d_in[8];
    const float* db2  = (const float*)d_in[9];
    float* out = (float*)d_out;

    cudaFuncSetAttribute(k_encode, cudaFuncAttributeMaxDynamicSharedMemorySize, SMEM1_BYTES);
    cudaFuncSetAttribute(k_decode, cudaFuncAttributeMaxDynamicSharedMemorySize, SMEM2_BYTES);

    k_encode<<<GRID1, THREADS1, SMEM1_BYTES>>>(x, ew1, eb1, ew2, eb2, cb);
    k_decode<<<GRID1, THREADS1, SMEM2_BYTES>>>(x, cb, dw1, db1, dw2, db2, out);
    k_final<<<1, 32>>>(out);
}

// round 6
// speedup vs baseline: 1.4972x; 1.4972x over previous
#include <cuda_runtime.h>
#include <cuda_bf16.h>
#include <cstdint>

#define B_TOTAL 262144
#define IN_DIM 28
#define HID 128
#define LAT 64
#define NCODES 512
#define GRID1 148
#define TILE_M 128
#define NTILES (B_TOTAL / TILE_M)   // 2048

// ---------------- encode kernel config ----------------
#define ETHREADS 512
#define EWARPS 16
#define ROWB 4

// smem byte offsets (128B rows, XOR-swizzled at 16B granularity)
#define OF_CBH  0
#define OF_CBL  (OF_CBH + NCODES * 128)            // 65536
#define OF_ZBH  (OF_CBL + NCODES * 128)            // 131072
#define OF_ZBL  (OF_ZBH + TILE_M * 128)            // 147456
#define OF_W1   (OF_ZBL + TILE_M * 128)            // 163840
#define OF_B1   (OF_W1 + IN_DIM * HID * 4)         // 178176
#define OF_W2   (OF_B1 + HID * 4)                  // 178688
#define OF_B2   (OF_W2 + HID * LAT * 4)            // 211456
#define OF_E2   (OF_B2 + LAT * 4)                  // 211712
#define OF_REDV (OF_E2 + NCODES * 4)               // 213760
#define OF_REDI (OF_REDV + TILE_M * 2 * 4)         // 214784
#define OF_XS   (OF_REDI + TILE_M * 2 * 4)         // 215808
#define SMEM_E_BYTES (OF_XS + EWARPS * ROWB * IN_DIM * 4)  // 222976

// swizzled byte offset within a 128B-row tile: w = 4-byte word index (0..31)
#define SWZ_W(row, w)  ((row) * 128 + ((((w) >> 2) ^ ((row) & 7)) << 4) + ((w) & 3) * 4)
// swizzled byte offset at 16B-chunk granularity: ch = chunk index (0..7)
#define SWZ_C(row, ch) ((row) * 128 + ((((ch)) ^ ((row) & 7)) << 4))

// ---------------- decode kernel config ----------------
#define WARPS1 12
#define THREADS1 (WARPS1 * 32)
#define TOTWARPS (GRID1 * WARPS1)
#define OF_DW1  0
#define OF_DB1  (OF_DW1 + LAT * HID)
#define OF_DW2  (OF_DB1 + HID)
#define OF_DB2  (OF_DW2 + HID * IN_DIM)
#define OF_CB2  (OF_DB2 + IN_DIM)
#define OF_SCR2 (OF_CB2 + NCODES * LAT)
#define WSCR2   (ROWB * LAT + ROWB * HID)
#define SMEM2_FLOATS (OF_SCR2 + WARPS1 * WSCR2)
#define SMEM2_BYTES  (SMEM2_FLOATS * 4)

__device__ int   g_idx[B_TOTAL];
__device__ float g_vq_part[GRID1];
__device__ float g_rec_part[GRID1];

// ---------------- helpers ----------------
__device__ __forceinline__ uint32_t smem_u32_of(const void* p) {
    uint32_t a;
    asm("{ .reg .u64 t; cvta.to.shared.u64 t, %1; cvt.u32.u64 %0, t; }" : "=r"(a) : "l"(p));
    return a;
}
__device__ __forceinline__ void ldsm_x4(uint32_t* r, uint32_t addr) {
    asm volatile("ldmatrix.sync.aligned.m8n8.x4.shared.b16 {%0,%1,%2,%3}, [%4];"
        : "=r"(r[0]), "=r"(r[1]), "=r"(r[2]), "=r"(r[3]) : "r"(addr));
}
__device__ __forceinline__ void mma16816(float* d, const uint32_t* a, uint32_t b0, uint32_t b1) {
    asm volatile("mma.sync.aligned.m16n8k16.row.col.f32.bf16.bf16.f32 "
        "{%0,%1,%2,%3}, {%4,%5,%6,%7}, {%8,%9}, {%0,%1,%2,%3};"
        : "+f"(d[0]), "+f"(d[1]), "+f"(d[2]), "+f"(d[3])
        : "r"(a[0]), "r"(a[1]), "r"(a[2]), "r"(a[3]), "r"(b0), "r"(b1));
}
// split a float into bf16 hi + bf16 lo (lo = residual)
__device__ __forceinline__ void bf16_split(float v, __nv_bfloat16& hi, __nv_bfloat16& lo) {
    hi = __float2bfloat16(v);
    lo = __float2bfloat16(v - __bfloat162float(hi));
}

// ============================================================================
// K1: encoder scalar MLP + split-bf16 HMMA distance GEMM + argmin + vq
// ============================================================================
__global__ void __launch_bounds__(ETHREADS, 1)
k_encode(const float* __restrict__ x,
         const float* __restrict__ w1, const float* __restrict__ b1,
         const float* __restrict__ w2, const float* __restrict__ b2,
         const float* __restrict__ cb)
{
    extern __shared__ char smem[];
    const uint32_t smb = smem_u32_of(smem);

    float* s_w1   = (float*)(smem + OF_W1);
    float* s_b1   = (float*)(smem + OF_B1);
    float* s_w2   = (float*)(smem + OF_W2);
    float* s_b2   = (float*)(smem + OF_B2);
    float* s_e2   = (float*)(smem + OF_E2);
    float* s_redv = (float*)(smem + OF_REDV);
    int*   s_redi = (int*)(smem + OF_REDI);

    const int tid = threadIdx.x;
    const int warp = tid >> 5, lane = tid & 31;

    // --- stage weights / codebook (hi+lo split, swizzled 128B rows) ---
    for (int i = tid; i < IN_DIM * HID; i += ETHREADS) s_w1[i] = w1[i];
    for (int i = tid; i < HID;          i += ETHREADS) s_b1[i] = b1[i];
    for (int i = tid; i < HID * LAT;    i += ETHREADS) s_w2[i] = w2[i];
    for (int i = tid; i < LAT;          i += ETHREADS) s_b2[i] = b2[i];
    for (int i = tid; i < NCODES * 32; i += ETHREADS) {
        int c = i >> 5, w = i & 31;
        float f0 = cb[c * LAT + 2 * w], f1 = cb[c * LAT + 2 * w + 1];
        __nv_bfloat16 h0, l0, h1, l1;
        bf16_split(f0, h0, l0);
        bf16_split(f1, h1, l1);
        __nv_bfloat162 ph; ph.x = h0; ph.y = h1;
        __nv_bfloat162 pl; pl.x = l0; pl.y = l1;
        *(uint32_t*)(smem + OF_CBH + SWZ_W(c, w)) = *(uint32_t*)&ph;
        *(uint32_t*)(smem + OF_CBL + SWZ_W(c, w)) = *(uint32_t*)&pl;
    }
    for (int c = tid; c < NCODES; c += ETHREADS) {
        float s = 0.f;
        for (int k = 0; k < LAT; k++) { float v = cb[c * LAT + k]; s = fmaf(v, v, s); }
        s_e2[c] = s;
    }
    __syncthreads();

    float* xs = (float*)(smem + OF_XS) + warp * (ROWB * IN_DIM);

    // mma role constants
    const int rg = warp & 7;             // row-group (16 rows)
    const int nh = warp >> 3;            // which 256-code half
    const int R0 = rg * 16;
    const int g  = lane >> 2, t = lane & 3;
    const int a_row  = R0 + (lane & 7) + 8 * ((lane >> 3) & 1);
    const int a_ch   = lane >> 4;                 // 16B chunk parity from lane
    const int b_row0 = (lane & 7) + 8 * ((lane >> 4) & 1);
    const int b_ch   = (lane >> 3) & 1;

    float vq_local = 0.f;

    for (int tle = blockIdx.x; tle < NTILES; tle += GRID1) {
        // ---------- phase 1 (scalar): x -> h -> z, z split into bf16 hi/lo ----------
        for (int s = 0; s < 2; s++) {
            const int rbase = warp * 8 + s * 4;               // tile-local row
            const float* xg = x + (long)(tle * TILE_M + rbase) * IN_DIM;
            for (int i = lane; i < ROWB * IN_DIM; i += 32) xs[i] = xg[i];
            __syncwarp();

            // h = relu(x @ W1 + b1), h kept in registers (lane owns cols lane+32j)
            float hreg[ROWB][4];
            {
                float acc[ROWB][4];
                #pragma unroll
                for (int r = 0; r < ROWB; r++)
                    #pragma unroll
                    for (int j = 0; j < 4; j++) acc[r][j] = s_b1[lane + 32 * j];
                #pragma unroll 4
                for (int k = 0; k < IN_DIM; k++) {
                    float wv[4];
                    #pragma unroll
                    for (int j = 0; j < 4; j++) wv[j] = s_w1[k * HID + lane + 32 * j];
                    #pragma unroll
                    for (int r = 0; r < ROWB; r++) {
                        float xv = xs[r * IN_DIM + k];
                        #pragma unroll
                        for (int j = 0; j < 4; j++) acc[r][j] = fmaf(xv, wv[j], acc[r][j]);
                    }
                }
                #pragma unroll
                for (int r = 0; r < ROWB; r++)
                    #pragma unroll
                    for (int j = 0; j < 4; j++) hreg[r][j] = fmaxf(acc[r][j], 0.f);
            }

            // z = h @ W2 + b2 via shfl broadcast; lane owns cols (2*lane, 2*lane+1)
            {
                float acc0[ROWB], acc1[ROWB];
                float bb0 = s_b2[2 * lane], bb1 = s_b2[2 * lane + 1];
                #pragma unroll
                for (int r = 0; r < ROWB; r++) { acc0[r] = bb0; acc1[r] = bb1; }
                #pragma unroll
                for (int j = 0; j < 4; j++) {
                    #pragma unroll 8
                    for (int kk = 0; kk < 32; kk++) {
                        const int k = 32 * j + kk;
                        float2 wv = *(const float2*)&s_w2[k * LAT + 2 * lane];
                        #pragma unroll
                        for (int r = 0; r < ROWB; r++) {
                            float hv = __shfl_sync(0xffffffffu, hreg[r][j], kk);
                            acc0[r] = fmaf(hv, wv.x, acc0[r]);
                            acc1[r] = fmaf(hv, wv.y, acc1[r]);
                        }
                    }
                }
                #pragma unroll
                for (int r = 0; r < ROWB; r++) {
                    int row = rbase + r;
                    __nv_bfloat16 h0, l0, h1, l1;
                    bf16_split(acc0[r], h0, l0);
                    bf16_split(acc1[r], h1, l1);
                    __nv_bfloat162 ph; ph.x = h0; ph.y = h1;
                    __nv_bfloat162 pl; pl.x = l0; pl.y = l1;
                    *(uint32_t*)(smem + OF_ZBH + SWZ_W(row, lane)) = *(uint32_t*)&ph;
                    *(uint32_t*)(smem + OF_ZBL + SWZ_W(row, lane)) = *(uint32_t*)&pl;
                }
            }
            __syncwarp();
        }
        __syncthreads();

        // ---------- phase 2 (HMMA, 3-GEMM split): D[16,256] per warp ----------
        uint32_t afrH[4][4], afrL[4][4];
        #pragma unroll
        for (int kk = 0; kk < 4; kk++) {
            uint32_t off = SWZ_C(a_row, 2 * kk + a_ch);
            ldsm_x4(afrH[kk], smb + OF_ZBH + off);
            ldsm_x4(afrL[kk], smb + OF_ZBL + off);
        }

        float minvA = 3.4e38f, minvB = 3.4e38f;
        int   miniA = 0,       miniB = 0;

        #pragma unroll 1
        for (int ng = 0; ng < 4; ng++) {
            const int C0 = nh * 256 + ng * 64;
            float acc[8][4];
            #pragma unroll
            for (int ch = 0; ch < 8; ch++)
                #pragma unroll
                for (int u = 0; u < 4; u++) acc[ch][u] = 0.f;

            #pragma unroll
            for (int kk = 0; kk < 4; kk++) {
                #pragma unroll
                for (int pp = 0; pp < 4; pp++) {
                    const int rowb = C0 + pp * 16 + b_row0;
                    uint32_t off = SWZ_C(rowb, 2 * kk + b_ch);
                    uint32_t bH[4], bL[4];
                    // B stored [n][k]: NON-transposed ldmatrix yields the
                    // row.col B fragment (2 consecutive k per lane, fixed n).
                    ldsm_x4(bH, smb + OF_CBH + off);
                    ldsm_x4(bL, smb + OF_CBL + off);
                    mma16816(acc[2 * pp],     afrH[kk], bH[0], bH[1]);
                    mma16816(acc[2 * pp],     afrH[kk], bL[0], bL[1]);
                    mma16816(acc[2 * pp],     afrL[kk], bH[0], bH[1]);
                    mma16816(acc[2 * pp + 1], afrH[kk], bH[2], bH[3]);
                    mma16816(acc[2 * pp + 1], afrH[kk], bL[2], bL[3]);
                    mma16816(acc[2 * pp + 1], afrL[kk], bH[2], bH[3]);
                }
            }

            #pragma unroll
            for (int ch = 0; ch < 8; ch++) {
                int c0 = C0 + ch * 8 + 2 * t;
                float e0 = s_e2[c0], e1 = s_e2[c0 + 1];
                float d00 = fmaf(-2.f, acc[ch][0], e0);
                float d01 = fmaf(-2.f, acc[ch][1], e1);
                float d10 = fmaf(-2.f, acc[ch][2], e0);
                float d11 = fmaf(-2.f, acc[ch][3], e1);
                if (d00 < minvA) { minvA = d00; miniA = c0; }
                if (d01 < minvA) { minvA = d01; miniA = c0 + 1; }
                if (d10 < minvB) { minvB = d10; miniB = c0; }
                if (d11 < minvB) { minvB = d11; miniB = c0 + 1; }
            }
        }

        // reduce across the 4 lanes of each row-group (tie-break: smaller index)
        #pragma unroll
        for (int off = 1; off <= 2; off <<= 1) {
            float ov = __shfl_xor_sync(0xffffffffu, minvA, off);
            int   oi = __shfl_xor_sync(0xffffffffu, miniA, off);
            if (ov < minvA || (ov == minvA && oi < miniA)) { minvA = ov; miniA = oi; }
            ov = __shfl_xor_sync(0xffffffffu, minvB, off);
            oi = __shfl_xor_sync(0xffffffffu, miniB, off);
            if (ov < minvB || (ov == minvB && oi < miniB)) { minvB = ov; miniB = oi; }
        }
        if (t == 0) {
            s_redv[(R0 + g) * 2 + nh]     = minvA;
            s_redi[(R0 + g) * 2 + nh]     = miniA;
            s_redv[(R0 + 8 + g) * 2 + nh] = minvB;
            s_redi[(R0 + 8 + g) * 2 + nh] = miniB;
        }
        __syncthreads();

        // ---------- phase 3: combine halves, write idx, vq partial ----------
        if (tid < TILE_M) {
            float v0 = s_redv[tid * 2 + 0], v1 = s_redv[tid * 2 + 1];
            int   i0 = s_redi[tid * 2 + 0], i1 = s_redi[tid * 2 + 1];
            int mini = (v1 < v0 || (v1 == v0 && i1 < i0)) ? i1 : i0;
            g_idx[tle * TILE_M + tid] = mini;

            const float4* qv = (const float4*)(cb + mini * LAT);
            #pragma unroll 4
            for (int w2i = 0; w2i < 16; w2i++) {     // 2 words = 4 elems per iter
                uint32_t hA = *(uint32_t*)(smem + OF_ZBH + SWZ_W(tid, 2 * w2i));
                uint32_t lA = *(uint32_t*)(smem + OF_ZBL + SWZ_W(tid, 2 * w2i));
                uint32_t hB = *(uint32_t*)(smem + OF_ZBH + SWZ_W(tid, 2 * w2i + 1));
                uint32_t lB = *(uint32_t*)(smem + OF_ZBL + SWZ_W(tid, 2 * w2i + 1));
                __nv_bfloat162 hA2 = *(__nv_bfloat162*)&hA, lA2 = *(__nv_bfloat162*)&lA;
                __nv_bfloat162 hB2 = *(__nv_bfloat162*)&hB, lB2 = *(__nv_bfloat162*)&lB;
                float z0 = __bfloat162float(hA2.x) + __bfloat162float(lA2.x);
                float z1 = __bfloat162float(hA2.y) + __bfloat162float(lA2.y);
                float z2 = __bfloat162float(hB2.x) + __bfloat162float(lB2.x);
                float z3 = __bfloat162float(hB2.y) + __bfloat162float(lB2.y);
                float4 q = qv[w2i];
                float d0 = z0 - q.x, d1 = z1 - q.y, d2 = z2 - q.z, d3 = z3 - q.w;
                vq_local = fmaf(d0, d0, fmaf(d1, d1, fmaf(d2, d2, fmaf(d3, d3, vq_local))));
            }
        }
        __syncthreads();   // z tiles reusable next tile
    }

    // ---------- reduce vq ----------
    #pragma unroll
    for (int off = 16; off; off >>= 1) vq_local += __shfl_down_sync(0xffffffffu, vq_local, off);
    __syncthreads();
    if (lane == 0) s_redv[warp] = vq_local;
    __syncthreads();
    if (tid == 0) {
        float s = 0.f;
        for (int w = 0; w < EWARPS; w++) s += s_redv[w];
        g_vq_part[blockIdx.x] = s;
    }
}

// ============================================================================
// K2: decoder (q -> hd -> recon), recon write + recon-loss partials
// ============================================================================
__global__ void __launch_bounds__(THREADS1, 1)
k_decode(const float* __restrict__ x, const float* __restrict__ cb,
         const float* __restrict__ dw1, const float* __restrict__ db1,
         const float* __restrict__ dw2, const float* __restrict__ db2,
         float* __restrict__ out)
{
    extern __shared__ float sm[];
    float* s_w1 = sm + OF_DW1;
    float* s_b1 = sm + OF_DB1;
    float* s_w2 = sm + OF_DW2;
    float* s_b2 = sm + OF_DB2;
    float* s_cb = sm + OF_CB2;

    const int tid = threadIdx.x;
    for (int i = tid; i < LAT * HID;    i += THREADS1) s_w1[i] = dw1[i];
    for (int i = tid; i < HID;          i += THREADS1) s_b1[i] = db1[i];
    for (int i = tid; i < HID * IN_DIM; i += THREADS1) s_w2[i] = dw2[i];
    for (int i = tid; i < IN_DIM;       i += THREADS1) s_b2[i] = db2[i];
    for (int i = tid; i < NCODES * LAT; i += THREADS1) s_cb[i] = cb[i];
    __syncthreads();

    const int warp = tid >> 5, lane = tid & 31;
    float* qs  = sm + OF_SCR2 + warp * WSCR2;
    float* hds = qs + ROWB * LAT;

    const unsigned FULL = 0xffffffffu;
    float rec_local = 0.f;
    const int gw = blockIdx.x * WARPS1 + warp;

    for (int base = gw * ROWB; base < B_TOTAL; base += TOTWARPS * ROWB) {
        int idx4[ROWB];
        #pragma unroll
        for (int r = 0; r < ROWB; r++) idx4[r] = g_idx[base + r];
        #pragma unroll
        for (int r = 0; r < ROWB; r++) {
            qs[r * LAT + lane]      = s_cb[idx4[r] * LAT + lane];
            qs[r * LAT + lane + 32] = s_cb[idx4[r] * LAT + lane + 32];
        }
        __syncwarp();

        {
            float acc[ROWB][4];
            #pragma unroll
            for (int r = 0; r < ROWB; r++)
                #pragma unroll
                for (int jj = 0; jj < 4; jj++) acc[r][jj] = s_b1[lane + 32 * jj];
            #pragma unroll 4
            for (int k = 0; k < LAT; k++) {
                float wv[4];
                #pragma unroll
                for (int jj = 0; jj < 4; jj++) wv[jj] = s_w1[k * HID + lane + 32 * jj];
                #pragma unroll
                for (int r = 0; r < ROWB; r++) {
                    float qv = qs[r * LAT + k];
                    #pragma unroll
                    for (int jj = 0; jj < 4; jj++) acc[r][jj] = fmaf(qv, wv[jj], acc[r][jj]);
                }
            }
            #pragma unroll
            for (int r = 0; r < ROWB; r++)
                #pragma unroll
                for (int jj = 0; jj < 4; jj++)
                    hds[r * HID + lane + 32 * jj] = fmaxf(acc[r][jj], 0.f);
        }
        __syncwarp();

        if (lane < IN_DIM) {
            float acc[ROWB];
            #pragma unroll
            for (int r = 0; r < ROWB; r++) acc[r] = s_b2[lane];
            #pragma unroll 4
            for (int k = 0; k < HID; k++) {
                float wv = s_w2[k * IN_DIM + lane];
                #pragma unroll
                for (int r = 0; r < ROWB; r++) acc[r] = fmaf(hds[r * HID + k], wv, acc[r]);
            }
            #pragma unroll
            for (int r = 0; r < ROWB; r++) {
                long o = (long)(base + r) * IN_DIM + lane;
                out[o] = acc[r];
                float d = acc[r] - x[o];
                rec_local = fmaf(d, d, rec_local);
            }
        }
    }

    #pragma unroll
    for (int off = 16; off; off >>= 1) rec_local += __shfl_down_sync(FULL, rec_local, off);
    __syncthreads();
    if (lane == 0) sm[warp] = rec_local;
    __syncthreads();
    if (tid == 0) {
        float s = 0.f;
        for (int w = 0; w < WARPS1; w++) s += sm[w];
        g_rec_part[blockIdx.x] = s;
    }
}

// ============================================================================
// K3: finalize scalar losses
// ============================================================================
__global__ void k_final(float* __restrict__ out)
{
    if (threadIdx.x == 0) {
        double vs = 0.0, rs = 0.0;
        for (int i = 0; i < GRID1; i++) { vs += (double)g_vq_part[i]; rs += (double)g_rec_part[i]; }
        out[(long)B_TOTAL * IN_DIM]     = (float)(rs / ((double)B_TOTAL * IN_DIM));
        out[(long)B_TOTAL * IN_DIM + 1] = (float)(1.25 * vs / ((double)B_TOTAL * LAT));
    }
}

// ============================================================================
extern "C" void kernel_launch(void* const* d_in, const int* in_sizes, int n_in,
                              void* d_out, int out_size)
{
    const float* x    = (const float*)d_in[0];
    const float* ew1  = (const float*)d_in[1];
    const float* eb1  = (const float*)d_in[2];
    const float* ew2  = (const float*)d_in[3];
    const float* eb2  = (const float*)d_in[4];
    const float* cb   = (const float*)d_in[5];
    const float* dw1  = (const float*)d_in[6];
    const float* db1  = (const float*)d_in[7];
    const float* dw2  = (const float*)d_in[8];
    const float* db2  = (const float*)d_in[9];
    float* out = (float*)d_out;

    cudaFuncSetAttribute(k_encode, cudaFuncAttributeMaxDynamicSharedMemorySize, SMEM_E_BYTES);
    cudaFuncSetAttribute(k_decode, cudaFuncAttributeMaxDynamicSharedMemorySize, SMEM2_BYTES);

    k_encode<<<GRID1, ETHREADS, SMEM_E_BYTES>>>(x, ew1, eb1, ew2, eb2, cb);
    k_decode<<<GRID1, THREADS1, SMEM2_BYTES>>>(x, cb, dw1, db1, dw2, db2, out);
    k_final<<<1, 32>>>(out);
}

// round 7
// speedup vs baseline: 2.8724x; 1.9185x over previous
#include <cuda_runtime.h>
#include <cuda_bf16.h>
#include <cstdint>

#define B_TOTAL 262144
#define IN_DIM 28
#define HID 128
#define LAT 64
#define NCODES 512
#define GRID1 148
#define TILE_M 128
#define NTILES (B_TOTAL / TILE_M)   // 2048

#define ETHREADS 512
#define EWARPS 16

// ---- k_encode smem layout (bytes) ----
#define OF_CBL  0                                  // codebook lo bf16, 512x128B
#define OF_HT   (OF_CBL + NCODES * 128)            // 65536: h tiles HH0,HH1,HL0,HL1 (16KB each); CBH staging at init
#define OF_ZBH  (OF_HT + 65536)                    // 131072
#define OF_ZBL  (OF_ZBH + 16384)                   // 147456
#define OF_W2   (OF_ZBL + 16384)                   // 163840: W2H0,W2H1,W2L0,W2L1 (8KB each)
#define OF_W1   (OF_W2 + 32768)                    // 196608 fp32 28x128
#define OF_B1   (OF_W1 + IN_DIM * HID * 4)         // 210944
#define OF_B2   (OF_B1 + HID * 4)                  // 211456
#define OF_E2   (OF_B2 + LAT * 4)                  // 211712
#define OF_CAND (OF_E2 + NCODES * 4)               // 213760: u64[128]
#define OF_XS   (OF_CAND + TILE_M * 8)             // 214784
#define SMEM_E  (OF_XS + EWARPS * 4 * IN_DIM * 4)  // 221952

// XOR swizzle within 128B rows, 16B granularity
#define SWZ_W(row, w)  ((row) * 128 + ((((w) >> 2) ^ ((row) & 7)) << 4) + ((w) & 3) * 4)
#define SWZ_C(row, ch) ((row) * 128 + ((((ch)) ^ ((row) & 7)) << 4))

__device__ int    g_idx[B_TOTAL];
__device__ float  g_vq_part[GRID1];
__device__ float  g_rec_part[GRID1];
__device__ float  g_hd[NCODES * HID];
__device__ float  g_tbl[NCODES * IN_DIM];

// ---------------- helpers ----------------
__device__ __forceinline__ uint32_t smem_u32_of(const void* p) {
    uint32_t a;
    asm("{ .reg .u64 t; cvta.to.shared.u64 t, %1; cvt.u32.u64 %0, t; }" : "=r"(a) : "l"(p));
    return a;
}
__device__ __forceinline__ void ldsm_x4(uint32_t* r, uint32_t addr) {
    asm volatile("ldmatrix.sync.aligned.m8n8.x4.shared.b16 {%0,%1,%2,%3}, [%4];"
        : "=r"(r[0]), "=r"(r[1]), "=r"(r[2]), "=r"(r[3]) : "r"(addr));
}
__device__ __forceinline__ void mma16816(float* d, const uint32_t* a, uint32_t b0, uint32_t b1) {
    asm volatile("mma.sync.aligned.m16n8k16.row.col.f32.bf16.bf16.f32 "
        "{%0,%1,%2,%3}, {%4,%5,%6,%7}, {%8,%9}, {%0,%1,%2,%3};"
        : "+f"(d[0]), "+f"(d[1]), "+f"(d[2]), "+f"(d[3])
        : "r"(a[0]), "r"(a[1]), "r"(a[2]), "r"(a[3]), "r"(b0), "r"(b1));
}
__device__ __forceinline__ void bf16_split(float v, __nv_bfloat16& hi, __nv_bfloat16& lo) {
    hi = __float2bfloat16(v);
    lo = __float2bfloat16(v - __bfloat162float(hi));
}
__device__ __forceinline__ uint32_t pack_hi(float a, float b) {
    __nv_bfloat162 p = __floats2bfloat162_rn(a, b);
    return *(uint32_t*)&p;
}
// monotone key: smaller distance first, then smaller index
__device__ __forceinline__ unsigned long long dist_key(float d, int c) {
    uint32_t u = __float_as_uint(d);
    u ^= (uint32_t)((int32_t)u >> 31) | 0x80000000u;
    return ((unsigned long long)u << 32) | (uint32_t)c;
}

// ============================================================================
// K1: encoder — scalar enc1, HMMA enc2, HMMA distance w/ reg-resident CBH
// ============================================================================
__global__ void __launch_bounds__(ETHREADS, 1)
k_encode(const float* __restrict__ x,
         const float* __restrict__ w1, const float* __restrict__ b1,
         const float* __restrict__ w2, const float* __restrict__ b2,
         const float* __restrict__ cb)
{
    extern __shared__ char smem[];
    const uint32_t smb = smem_u32_of(smem);

    float* s_w1 = (float*)(smem + OF_W1);
    float* s_b1 = (float*)(smem + OF_B1);
    float* s_b2 = (float*)(smem + OF_B2);
    float* s_e2 = (float*)(smem + OF_E2);
    unsigned long long* s_cand = (unsigned long long*)(smem + OF_CAND);

    const int tid = threadIdx.x;
    const int warp = tid >> 5, lane = tid & 31;

    // ---- init: stage weights, codebook (hi->HT staging, lo->CBL), W2 split ----
    for (int i = tid; i < IN_DIM * HID; i += ETHREADS) s_w1[i] = w1[i];
    for (int i = tid; i < HID;          i += ETHREADS) s_b1[i] = b1[i];
    for (int i = tid; i < LAT;          i += ETHREADS) s_b2[i] = b2[i];
    for (int i = tid; i < NCODES * 32; i += ETHREADS) {
        int c = i >> 5, w = i & 31;
        float f0 = cb[c * LAT + 2 * w], f1 = cb[c * LAT + 2 * w + 1];
        __nv_bfloat16 h0, l0, h1, l1;
        bf16_split(f0, h0, l0); bf16_split(f1, h1, l1);
        __nv_bfloat162 ph; ph.x = h0; ph.y = h1;
        __nv_bfloat162 pl; pl.x = l0; pl.y = l1;
        *(uint32_t*)(smem + OF_HT  + SWZ_W(c, w)) = *(uint32_t*)&ph;  // CBH staging
        *(uint32_t*)(smem + OF_CBL + SWZ_W(c, w)) = *(uint32_t*)&pl;
    }
    // W2^T split: B[n][k], two 64-k halves per component
    for (int i = tid; i < LAT * 64; i += ETHREADS) {
        int n = i >> 6, kw = i & 63;
        int k0 = 2 * kw;
        float f0 = w2[k0 * LAT + n], f1 = w2[(k0 + 1) * LAT + n];
        __nv_bfloat16 h0, l0, h1, l1;
        bf16_split(f0, h0, l0); bf16_split(f1, h1, l1);
        __nv_bfloat162 ph; ph.x = h0; ph.y = h1;
        __nv_bfloat162 pl; pl.x = l0; pl.y = l1;
        int khalf = kw >> 5, w = kw & 31;
        *(uint32_t*)(smem + OF_W2 + khalf * 8192 + SWZ_W(n, w))         = *(uint32_t*)&ph;
        *(uint32_t*)(smem + OF_W2 + 16384 + khalf * 8192 + SWZ_W(n, w)) = *(uint32_t*)&pl;
    }
    for (int c = tid; c < NCODES; c += ETHREADS) {
        float s = 0.f;
        for (int k = 0; k < LAT; k++) { float v = cb[c * LAT + k]; s = fmaf(v, v, s); }
        s_e2[c] = s;
    }
    if (tid < TILE_M) s_cand[tid] = ~0ULL;
    __syncthreads();

    // mma lane-role constants
    const int g = lane >> 2, t = lane & 3;
    const int a_roff = (lane & 7) + 8 * ((lane >> 3) & 1);
    const int a_ch   = lane >> 4;
    const int b_row0 = (lane & 7) + 8 * ((lane >> 4) & 1);
    const int b_ch   = (lane >> 3) & 1;

    // ---- load this warp's CBH fragments into registers (32 regs) ----
    uint32_t bregH[4][4][2];
    #pragma unroll
    for (int pp = 0; pp < 2; pp++)
        #pragma unroll
        for (int kk = 0; kk < 4; kk++) {
            uint32_t r4[4];
            ldsm_x4(r4, smb + OF_HT + SWZ_C(warp * 32 + pp * 16 + b_row0, 2 * kk + b_ch));
            bregH[2 * pp][kk][0] = r4[0];     bregH[2 * pp][kk][1] = r4[1];
            bregH[2 * pp + 1][kk][0] = r4[2]; bregH[2 * pp + 1][kk][1] = r4[3];
        }
    __syncthreads();   // HT region now free for h tiles

    float* xs = (float*)(smem + OF_XS) + warp * (4 * IN_DIM);
    float vq_local = 0.f;

    for (int tle = blockIdx.x; tle < NTILES; tle += GRID1) {
        // -------- P1: enc1 scalar, h split into HT tiles --------
        #pragma unroll
        for (int s = 0; s < 2; s++) {
            const int rbase = warp * 8 + s * 4;
            const float* xg = x + (long)(tle * TILE_M + rbase) * IN_DIM;
            for (int i = lane; i < 4 * IN_DIM; i += 32) xs[i] = xg[i];
            __syncwarp();

            float acc[4][4];
            #pragma unroll
            for (int r = 0; r < 4; r++) {
                acc[r][0] = s_b1[2 * lane];     acc[r][1] = s_b1[2 * lane + 1];
                acc[r][2] = s_b1[64 + 2 * lane]; acc[r][3] = s_b1[65 + 2 * lane];
            }
            #pragma unroll 4
            for (int k = 0; k < IN_DIM; k++) {
                float2 w01 = *(const float2*)&s_w1[k * HID + 2 * lane];
                float2 w23 = *(const float2*)&s_w1[k * HID + 64 + 2 * lane];
                #pragma unroll
                for (int r = 0; r < 4; r++) {
                    float xv = xs[r * IN_DIM + k];
                    acc[r][0] = fmaf(xv, w01.x, acc[r][0]);
                    acc[r][1] = fmaf(xv, w01.y, acc[r][1]);
                    acc[r][2] = fmaf(xv, w23.x, acc[r][2]);
                    acc[r][3] = fmaf(xv, w23.y, acc[r][3]);
                }
            }
            #pragma unroll
            for (int r = 0; r < 4; r++) {
                int row = rbase + r;
                float h0 = fmaxf(acc[r][0], 0.f), h1 = fmaxf(acc[r][1], 0.f);
                float h2 = fmaxf(acc[r][2], 0.f), h3 = fmaxf(acc[r][3], 0.f);
                __nv_bfloat16 a0, b0, a1, b1v, a2, b2v, a3, b3;
                bf16_split(h0, a0, b0); bf16_split(h1, a1, b1v);
                bf16_split(h2, a2, b2v); bf16_split(h3, a3, b3);
                __nv_bfloat162 p;
                p.x = a0; p.y = a1; *(uint32_t*)(smem + OF_HT + SWZ_W(row, lane)) = *(uint32_t*)&p;
                p.x = b0; p.y = b1v; *(uint32_t*)(smem + OF_HT + 32768 + SWZ_W(row, lane)) = *(uint32_t*)&p;
                p.x = a2; p.y = a3; *(uint32_t*)(smem + OF_HT + 16384 + SWZ_W(row, lane)) = *(uint32_t*)&p;
                p.x = b2v; p.y = b3; *(uint32_t*)(smem + OF_HT + 49152 + SWZ_W(row, lane)) = *(uint32_t*)&p;
            }
        }
        __syncthreads();

        // -------- P2: enc2 split-bf16 MMA: z = h @ W2 + b2 --------
        {
            const int rb2 = warp >> 1, nhf = warp & 1;
            const int a_row2 = rb2 * 16 + a_roff;
            float acc2[4][4];
            #pragma unroll
            for (int nb = 0; nb < 4; nb++)
                #pragma unroll
                for (int u = 0; u < 4; u++) acc2[nb][u] = 0.f;

            #pragma unroll
            for (int khalf = 0; khalf < 2; khalf++) {
                #pragma unroll
                for (int kk = 0; kk < 4; kk++) {
                    uint32_t aH[4], aL[4];
                    uint32_t offA = SWZ_C(a_row2, 2 * kk + a_ch);
                    ldsm_x4(aH, smb + OF_HT + khalf * 16384 + offA);
                    ldsm_x4(aL, smb + OF_HT + 32768 + khalf * 16384 + offA);
                    #pragma unroll
                    for (int pp = 0; pp < 2; pp++) {
                        int nrow = nhf * 32 + pp * 16 + b_row0;
                        uint32_t offB = SWZ_C(nrow, 2 * kk + b_ch);
                        uint32_t bH[4], bL[4];
                        ldsm_x4(bH, smb + OF_W2 + khalf * 8192 + offB);
                        ldsm_x4(bL, smb + OF_W2 + 16384 + khalf * 8192 + offB);
                        mma16816(acc2[2 * pp], aH, bH[0], bH[1]);
                        mma16816(acc2[2 * pp], aH, bL[0], bL[1]);
                        mma16816(acc2[2 * pp], aL, bH[0], bH[1]);
                        mma16816(acc2[2 * pp + 1], aH, bH[2], bH[3]);
                        mma16816(acc2[2 * pp + 1], aH, bL[2], bL[3]);
                        mma16816(acc2[2 * pp + 1], aL, bH[2], bH[3]);
                    }
                }
            }
            // epilogue: +b2, split, store ZB
            #pragma unroll
            for (int nb = 0; nb < 4; nb++) {
                int c0 = nhf * 32 + nb * 8 + 2 * t;
                int w = c0 >> 1;
                float bb0 = s_b2[c0], bb1 = s_b2[c0 + 1];
                int rA = rb2 * 16 + g, rB = rA + 8;
                float z00 = acc2[nb][0] + bb0, z01 = acc2[nb][1] + bb1;
                float z10 = acc2[nb][2] + bb0, z11 = acc2[nb][3] + bb1;
                __nv_bfloat16 h0, l0, h1, l1;
                bf16_split(z00, h0, l0); bf16_split(z01, h1, l1);
                __nv_bfloat162 p;
                p.x = h0; p.y = h1; *(uint32_t*)(smem + OF_ZBH + SWZ_W(rA, w)) = *(uint32_t*)&p;
                p.x = l0; p.y = l1; *(uint32_t*)(smem + OF_ZBL + SWZ_W(rA, w)) = *(uint32_t*)&p;
                bf16_split(z10, h0, l0); bf16_split(z11, h1, l1);
                p.x = h0; p.y = h1; *(uint32_t*)(smem + OF_ZBH + SWZ_W(rB, w)) = *(uint32_t*)&p;
                p.x = l0; p.y = l1; *(uint32_t*)(smem + OF_ZBL + SWZ_W(rB, w)) = *(uint32_t*)&p;
            }
        }
        __syncthreads();

        // -------- P3: distance MMA over row-blocks; warp owns 32 codes --------
        #pragma unroll 1
        for (int rb = 0; rb < 8; rb++) {
            const int R0 = rb * 16;
            const int a_row3 = R0 + a_roff;
            uint32_t afH[4][4], afL[4][4];
            #pragma unroll
            for (int kk = 0; kk < 4; kk++) {
                uint32_t off = SWZ_C(a_row3, 2 * kk + a_ch);
                ldsm_x4(afH[kk], smb + OF_ZBH + off);
                ldsm_x4(afL[kk], smb + OF_ZBL + off);
            }
            float acc3[4][4];
            #pragma unroll
            for (int nb = 0; nb < 4; nb++)
                #pragma unroll
                for (int u = 0; u < 4; u++) acc3[nb][u] = 0.f;

            #pragma unroll
            for (int kk = 0; kk < 4; kk++) {
                #pragma unroll
                for (int pp = 0; pp < 2; pp++) {
                    uint32_t bL[4];
                    ldsm_x4(bL, smb + OF_CBL + SWZ_C(warp * 32 + pp * 16 + b_row0, 2 * kk + b_ch));
                    mma16816(acc3[2 * pp],     afH[kk], bL[0], bL[1]);   // zH*eL
                    mma16816(acc3[2 * pp + 1], afH[kk], bL[2], bL[3]);
                }
                #pragma unroll
                for (int nb = 0; nb < 4; nb++) {
                    mma16816(acc3[nb], afH[kk], bregH[nb][kk][0], bregH[nb][kk][1]);  // zH*eH
                    mma16816(acc3[nb], afL[kk], bregH[nb][kk][0], bregH[nb][kk][1]);  // zL*eH
                }
            }
            // per-lane best over its 8 code-cols, for rows R0+g and R0+8+g
            float mA = 3.4e38f, mB = 3.4e38f; int iA = 0, iB = 0;
            #pragma unroll
            for (int nb = 0; nb < 4; nb++) {
                int c0 = warp * 32 + nb * 8 + 2 * t;
                float e0 = s_e2[c0], e1 = s_e2[c0 + 1];
                float d00 = fmaf(-2.f, acc3[nb][0], e0);
                float d01 = fmaf(-2.f, acc3[nb][1], e1);
                float d10 = fmaf(-2.f, acc3[nb][2], e0);
                float d11 = fmaf(-2.f, acc3[nb][3], e1);
                if (d00 < mA) { mA = d00; iA = c0; }
                if (d01 < mA) { mA = d01; iA = c0 + 1; }
                if (d10 < mB) { mB = d10; iB = c0; }
                if (d11 < mB) { mB = d11; iB = c0 + 1; }
            }
            #pragma unroll
            for (int off = 1; off <= 2; off <<= 1) {
                float ov = __shfl_xor_sync(0xffffffffu, mA, off);
                int   oi = __shfl_xor_sync(0xffffffffu, iA, off);
                if (ov < mA || (ov == mA && oi < iA)) { mA = ov; iA = oi; }
                ov = __shfl_xor_sync(0xffffffffu, mB, off);
                oi = __shfl_xor_sync(0xffffffffu, iB, off);
                if (ov < mB || (ov == mB && oi < iB)) { mB = ov; iB = oi; }
            }
            if (t == 0) {
                atomicMin(&s_cand[R0 + g], dist_key(mA, iA));
                atomicMin(&s_cand[R0 + 8 + g], dist_key(mB, iB));
            }
        }
        __syncthreads();

        // -------- P4: write idx, vq partial, reset cand --------
        if (tid < TILE_M) {
            unsigned long long key = s_cand[tid];
            int mini = (int)(key & 0xFFFFFFFFu);
            g_idx[tle * TILE_M + tid] = mini;
            s_cand[tid] = ~0ULL;

            const float2* qv = (const float2*)(cb + mini * LAT);
            #pragma unroll 8
            for (int w = 0; w < 32; w++) {
                uint32_t hu = *(uint32_t*)(smem + OF_ZBH + SWZ_W(tid, w));
                uint32_t lu = *(uint32_t*)(smem + OF_ZBL + SWZ_W(tid, w));
                __nv_bfloat162 h2 = *(__nv_bfloat162*)&hu, l2 = *(__nv_bfloat162*)&lu;
                float z0 = __bfloat162float(h2.x) + __bfloat162float(l2.x);
                float z1 = __bfloat162float(h2.y) + __bfloat162float(l2.y);
                float2 q = qv[w];
                float d0 = z0 - q.x, d1 = z1 - q.y;
                vq_local = fmaf(d0, d0, fmaf(d1, d1, vq_local));
            }
        }
        __syncthreads();
    }

    // ---- reduce vq ----
    #pragma unroll
    for (int off = 16; off; off >>= 1) vq_local += __shfl_down_sync(0xffffffffu, vq_local, off);
    __syncthreads();
    float* s_red = (float*)(smem + OF_XS);
    if (lane == 0) s_red[warp] = vq_local;
    __syncthreads();
    if (tid == 0) {
        float s = 0.f;
        for (int w = 0; w < EWARPS; w++) s += s_red[w];
        g_vq_part[blockIdx.x] = s;
    }
}

// ============================================================================
// K2a/K2b: decoder table for 512 codes (exact fp32)
// ============================================================================
__global__ void k_hd(const float* __restrict__ cb,
                     const float* __restrict__ dw1, const float* __restrict__ db1)
{
    int gid = blockIdx.x * blockDim.x + threadIdx.x;   // NCODES*HID threads
    int c = gid >> 7, j = gid & 127;
    float acc = db1[j];
    const float* q = cb + c * LAT;
    #pragma unroll 8
    for (int k = 0; k < LAT; k++) acc = fmaf(q[k], dw1[k * HID + j], acc);
    g_hd[gid] = fmaxf(acc, 0.f);
}

__global__ void k_tbl(const float* __restrict__ dw2, const float* __restrict__ db2)
{
    int gid = blockIdx.x * blockDim.x + threadIdx.x;   // NCODES*IN_DIM threads
    int c = gid / IN_DIM, j = gid - c * IN_DIM;
    float acc = db2[j];
    const float* hd = g_hd + c * HID;
    #pragma unroll 8
    for (int k = 0; k < HID; k++) acc = fmaf(hd[k], dw2[k * IN_DIM + j], acc);
    g_tbl[gid] = acc;
}

// ============================================================================
// K3: gather recon from table, write out, recon-loss partials
// ============================================================================
#define OUT_THREADS 512
__global__ void __launch_bounds__(OUT_THREADS)
k_out(const float* __restrict__ x, float* __restrict__ out)
{
    const int total4 = B_TOTAL * (IN_DIM / 4);          // 7 float4 per row
    const float4* x4 = (const float4*)x;
    float4* o4 = (float4*)out;
    const float4* t4 = (const float4*)g_tbl;

    float rec = 0.f;
    for (int f4 = blockIdx.x * OUT_THREADS + threadIdx.x; f4 < total4;
         f4 += GRID1 * OUT_THREADS) {
        int row = f4 / 7;
        int w = f4 - row * 7;
        int idx = g_idx[row];
        float4 tv = t4[idx * 7 + w];
        float4 xv = x4[f4];
        o4[f4] = tv;
        float d0 = tv.x - xv.x, d1 = tv.y - xv.y, d2 = tv.z - xv.z, d3 = tv.w - xv.w;
        rec = fmaf(d0, d0, fmaf(d1, d1, fmaf(d2, d2, fmaf(d3, d3, rec))));
    }
    __shared__ float s_red[OUT_THREADS / 32];
    #pragma unroll
    for (int off = 16; off; off >>= 1) rec += __shfl_down_sync(0xffffffffu, rec, off);
    if ((threadIdx.x & 31) == 0) s_red[threadIdx.x >> 5] = rec;
    __syncthreads();
    if (threadIdx.x == 0) {
        float s = 0.f;
        for (int w = 0; w < OUT_THREADS / 32; w++) s += s_red[w];
        g_rec_part[blockIdx.x] = s;
    }
}

// ============================================================================
// K4: finalize scalar losses
// ============================================================================
__global__ void k_final(float* __restrict__ out)
{
    if (threadIdx.x == 0) {
        double vs = 0.0, rs = 0.0;
        for (int i = 0; i < GRID1; i++) { vs += (double)g_vq_part[i]; rs += (double)g_rec_part[i]; }
        out[(long)B_TOTAL * IN_DIM]     = (float)(rs / ((double)B_TOTAL * IN_DIM));
        out[(long)B_TOTAL * IN_DIM + 1] = (float)(1.25 * vs / ((double)B_TOTAL * LAT));
    }
}

// ============================================================================
extern "C" void kernel_launch(void* const* d_in, const int* in_sizes, int n_in,
                              void* d_out, int out_size)
{
    const float* x    = (const float*)d_in[0];
    const float* ew1  = (const float*)d_in[1];
    const float* eb1  = (const float*)d_in[2];
    const float* ew2  = (const float*)d_in[3];
    const float* eb2  = (const float*)d_in[4];
    const float* cb   = (const float*)d_in[5];
    const float* dw1  = (const float*)d_in[6];
    const float* db1  = (const float*)d_in[7];
    const float* dw2  = (const float*)d_in[8];
    const float* db2  = (const float*)d_in[9];
    float* out = (float*)d_out;

    cudaFuncSetAttribute(k_encode, cudaFuncAttributeMaxDynamicSharedMemorySize, SMEM_E);

    k_hd<<<(NCODES * HID) / 256, 256>>>(cb, dw1, db1);
    k_tbl<<<(NCODES * IN_DIM) / 256, 256>>>(dw2, db2);
    k_encode<<<GRID1, ETHREADS, SMEM_E>>>(x, ew1, eb1, ew2, eb2, cb);
    k_out<<<GRID1, OUT_THREADS>>>(x, out);
    k_final<<<1, 32>>>(out);
}

// round 8
// speedup vs baseline: 3.2451x; 1.1298x over previous
#include <cuda_runtime.h>
#include <cuda_bf16.h>
#include <cstdint>

#define B_TOTAL 262144
#define IN_DIM 28
#define HID 128
#define LAT 64
#define NCODES 512
#define GRID1 148
#define TILE_M 128
#define NTILES (B_TOTAL / TILE_M)   // 2048

#define ETHREADS 512
#define EWARPS 16

// ---- k_encode smem layout (bytes) ----
#define OF_CBL   0                                  // codebook lo bf16, 512x128B
#define OF_HT    (OF_CBL + NCODES * 128)            // 65536: h tiles HH0,HH1,HL0,HL1 (16K each); CBH staging at init
#define OF_ZBH   (OF_HT + 65536)                    // 131072 (aliased: XBH during stage-x/P1)
#define OF_ZBL   (OF_ZBH + 16384)                   // 147456 (aliased: XBL)
#define OF_XBH   OF_ZBH
#define OF_XBL   OF_ZBL
#define OF_W2    (OF_ZBL + 16384)                   // 163840: W2H0,W2H1,W2L0,W2L1 (8K each)
#define OF_W1TH  (OF_W2 + 32768)                    // 196608: W1^T hi [128n][32k] 64B rows
#define OF_W1TL  (OF_W1TH + 8192)                   // 204800
#define OF_B1    (OF_W1TL + 8192)                   // 212992
#define OF_B2    (OF_B1 + HID * 4)                  // 213504
#define OF_E2    (OF_B2 + LAT * 4)                  // 213760
#define OF_CAND  (OF_E2 + NCODES * 4)               // 215808: u64[128]
#define OF_Z2    (OF_CAND + TILE_M * 8)             // 216832: float[128][2]
#define SMEM_E   (OF_Z2 + TILE_M * 2 * 4)           // 217856

// XOR swizzle, 128B rows (16B granularity)
#define SWZ_W(row, w)  ((row) * 128 + ((((w) >> 2) ^ ((row) & 7)) << 4) + ((w) & 3) * 4)
#define SWZ_C(row, ch) ((row) * 128 + ((((ch)) ^ ((row) & 7)) << 4))
// XOR swizzle, 64B rows (4 chunks of 16B)
#define SWZ64_W(row, w)  ((row) * 64 + ((((w) >> 2) ^ (((row) >> 1) & 3)) << 4) + ((w) & 3) * 4)
#define SWZ64_C(row, ch) ((row) * 64 + ((((ch)) ^ (((row) >> 1) & 3)) << 4))

#define KOUT_GRID 592

__device__ int    g_idx[B_TOTAL];
__device__ float  g_vq_part[GRID1];
__device__ float  g_rec_part[KOUT_GRID];
__device__ float  g_hd[NCODES * HID];
__device__ float  g_tbl[NCODES * IN_DIM];

// ---------------- helpers ----------------
__device__ __forceinline__ uint32_t smem_u32_of(const void* p) {
    uint32_t a;
    asm("{ .reg .u64 t; cvta.to.shared.u64 t, %1; cvt.u32.u64 %0, t; }" : "=r"(a) : "l"(p));
    return a;
}
__device__ __forceinline__ void ldsm_x4(uint32_t* r, uint32_t addr) {
    asm volatile("ldmatrix.sync.aligned.m8n8.x4.shared.b16 {%0,%1,%2,%3}, [%4];"
        : "=r"(r[0]), "=r"(r[1]), "=r"(r[2]), "=r"(r[3]) : "r"(addr));
}
__device__ __forceinline__ void mma16816(float* d, const uint32_t* a, uint32_t b0, uint32_t b1) {
    asm volatile("mma.sync.aligned.m16n8k16.row.col.f32.bf16.bf16.f32 "
        "{%0,%1,%2,%3}, {%4,%5,%6,%7}, {%8,%9}, {%0,%1,%2,%3};"
        : "+f"(d[0]), "+f"(d[1]), "+f"(d[2]), "+f"(d[3])
        : "r"(a[0]), "r"(a[1]), "r"(a[2]), "r"(a[3]), "r"(b0), "r"(b1));
}
__device__ __forceinline__ void bf16_split(float v, __nv_bfloat16& hi, __nv_bfloat16& lo) {
    hi = __float2bfloat16(v);
    lo = __float2bfloat16(v - __bfloat162float(hi));
}
__device__ __forceinline__ uint32_t pack2_split_hi(float a, float b, uint32_t& lo_out) {
    __nv_bfloat16 ha, la, hb, lb;
    bf16_split(a, ha, la); bf16_split(b, hb, lb);
    __nv_bfloat162 ph; ph.x = ha; ph.y = hb;
    __nv_bfloat162 pl; pl.x = la; pl.y = lb;
    lo_out = *(uint32_t*)&pl;
    return *(uint32_t*)&ph;
}
// monotone key: smaller distance first, then smaller index
__device__ __forceinline__ unsigned long long dist_key(float d, int c) {
    uint32_t u = __float_as_uint(d);
    u ^= (uint32_t)((int32_t)u >> 31) | 0x80000000u;
    return ((unsigned long long)u << 32) | (uint32_t)c;
}
__device__ __forceinline__ float dist_unkey(unsigned long long key) {
    uint32_t u = (uint32_t)(key >> 32);
    u = (u & 0x80000000u) ? (u ^ 0x80000000u) : ~u;
    return __uint_as_float(u);
}

// ============================================================================
// K1: encoder — MMA enc1, MMA enc2, MMA distance w/ reg-resident CBH
// ============================================================================
__global__ void __launch_bounds__(ETHREADS, 1)
k_encode(const float* __restrict__ x,
         const float* __restrict__ w1, const float* __restrict__ b1,
         const float* __restrict__ w2, const float* __restrict__ b2,
         const float* __restrict__ cb)
{
    extern __shared__ char smem[];
    const uint32_t smb = smem_u32_of(smem);

    float* s_b1 = (float*)(smem + OF_B1);
    float* s_b2 = (float*)(smem + OF_B2);
    float* s_e2 = (float*)(smem + OF_E2);
    float* s_z2 = (float*)(smem + OF_Z2);
    unsigned long long* s_cand = (unsigned long long*)(smem + OF_CAND);

    const int tid = threadIdx.x;
    const int warp = tid >> 5, lane = tid & 31;

    // ---- init ----
    for (int i = tid; i < HID; i += ETHREADS) s_b1[i] = b1[i];
    for (int i = tid; i < LAT; i += ETHREADS) s_b2[i] = b2[i];
    // codebook split: hi -> HT staging, lo -> CBL (128B rows)
    for (int i = tid; i < NCODES * 32; i += ETHREADS) {
        int c = i >> 5, w = i & 31;
        uint32_t lo;
        uint32_t hi = pack2_split_hi(cb[c * LAT + 2 * w], cb[c * LAT + 2 * w + 1], lo);
        *(uint32_t*)(smem + OF_HT  + SWZ_W(c, w)) = hi;
        *(uint32_t*)(smem + OF_CBL + SWZ_W(c, w)) = lo;
    }
    // W2^T split: [64 n][128 k] as two k-halves, 128B rows
    for (int i = tid; i < LAT * 64; i += ETHREADS) {
        int n = i >> 6, kw = i & 63;
        uint32_t lo;
        uint32_t hi = pack2_split_hi(w2[2 * kw * LAT + n], w2[(2 * kw + 1) * LAT + n], lo);
        int khalf = kw >> 5, w = kw & 31;
        *(uint32_t*)(smem + OF_W2 + khalf * 8192 + SWZ_W(n, w))         = hi;
        *(uint32_t*)(smem + OF_W2 + 16384 + khalf * 8192 + SWZ_W(n, w)) = lo;
    }
    // W1^T split: [128 n][32 k], 64B rows; pad k 28..31 with zeros
    for (int i = tid; i < HID * 14; i += ETHREADS) {
        int n = i / 14, kw = i - n * 14;
        uint32_t lo;
        uint32_t hi = pack2_split_hi(w1[2 * kw * HID + n], w1[(2 * kw + 1) * HID + n], lo);
        *(uint32_t*)(smem + OF_W1TH + SWZ64_W(n, kw)) = hi;
        *(uint32_t*)(smem + OF_W1TL + SWZ64_W(n, kw)) = lo;
    }
    for (int i = tid; i < HID * 2; i += ETHREADS) {
        int n = i >> 1, w = 14 + (i & 1);
        *(uint32_t*)(smem + OF_W1TH + SWZ64_W(n, w)) = 0;
        *(uint32_t*)(smem + OF_W1TL + SWZ64_W(n, w)) = 0;
    }
    for (int c = tid; c < NCODES; c += ETHREADS) {
        float s = 0.f;
        for (int k = 0; k < LAT; k++) { float v = cb[c * LAT + k]; s = fmaf(v, v, s); }
        s_e2[c] = s;
    }
    if (tid < TILE_M) s_cand[tid] = ~0ULL;
    __syncthreads();

    // mma lane-role constants
    const int g = lane >> 2, t = lane & 3;
    const int a_roff = (lane & 7) + 8 * ((lane >> 3) & 1);
    const int a_ch   = lane >> 4;
    const int b_row0 = (lane & 7) + 8 * ((lane >> 4) & 1);
    const int b_ch   = (lane >> 3) & 1;

    // ---- this warp's CBH fragments -> registers ----
    uint32_t bregH[4][4][2];
    #pragma unroll
    for (int pp = 0; pp < 2; pp++)
        #pragma unroll
        for (int kk = 0; kk < 4; kk++) {
            uint32_t r4[4];
            ldsm_x4(r4, smb + OF_HT + SWZ_C(warp * 32 + pp * 16 + b_row0, 2 * kk + b_ch));
            bregH[2 * pp][kk][0] = r4[0];     bregH[2 * pp][kk][1] = r4[1];
            bregH[2 * pp + 1][kk][0] = r4[2]; bregH[2 * pp + 1][kk][1] = r4[3];
        }
    __syncthreads();   // HT region free

    const int rbw = warp >> 1, nhf = warp & 1;   // shared by P1/P2 roles
    float vq_local = 0.f;

    for (int tle = blockIdx.x; tle < NTILES; tle += GRID1) {
        // -------- P0: stage x into XB hi/lo (aliases ZB; ZB dead) --------
        {
            const float4* xg4 = (const float4*)(x + (long)tle * TILE_M * IN_DIM);
            #pragma unroll
            for (int it = 0; it < 2; it++) {
                int i = tid + it * ETHREADS;
                if (i < TILE_M * 7) {
                    int row = i / 7, w4 = i - row * 7;
                    float4 v = xg4[i];
                    uint32_t lo0, lo1;
                    uint32_t hi0 = pack2_split_hi(v.x, v.y, lo0);
                    uint32_t hi1 = pack2_split_hi(v.z, v.w, lo1);
                    uint64_t hp = (uint64_t)hi0 | ((uint64_t)hi1 << 32);
                    uint64_t lp = (uint64_t)lo0 | ((uint64_t)lo1 << 32);
                    *(uint64_t*)(smem + OF_XBH + SWZ64_W(row, 2 * w4)) = hp;
                    *(uint64_t*)(smem + OF_XBL + SWZ64_W(row, 2 * w4)) = lp;
                }
            }
            if (tid < TILE_M * 2) {            // zero pad k 28..31
                int row = tid >> 1, w = 14 + (tid & 1);
                *(uint32_t*)(smem + OF_XBH + SWZ64_W(row, w)) = 0;
                *(uint32_t*)(smem + OF_XBL + SWZ64_W(row, w)) = 0;
            }
        }
        __syncthreads();   // A

        // -------- P1: enc1 MMA: h = relu(x @ W1 + b1) -> HT tiles --------
        {
            const int R0 = rbw * 16;
            float acc[8][4];
            #pragma unroll
            for (int nb = 0; nb < 8; nb++)
                #pragma unroll
                for (int u = 0; u < 4; u++) acc[nb][u] = 0.f;

            #pragma unroll
            for (int kk = 0; kk < 2; kk++) {
                uint32_t aH[4], aL[4];
                uint32_t offA = SWZ64_C(R0 + a_roff, 2 * kk + a_ch);
                ldsm_x4(aH, smb + OF_XBH + offA);
                ldsm_x4(aL, smb + OF_XBL + offA);
                #pragma unroll
                for (int pp = 0; pp < 4; pp++) {
                    int nrow = nhf * 64 + pp * 16 + b_row0;
                    uint32_t offB = SWZ64_C(nrow, 2 * kk + b_ch);
                    uint32_t bH[4], bL[4];
                    ldsm_x4(bH, smb + OF_W1TH + offB);
                    ldsm_x4(bL, smb + OF_W1TL + offB);
                    mma16816(acc[2 * pp], aH, bH[0], bH[1]);
                    mma16816(acc[2 * pp], aH, bL[0], bL[1]);
                    mma16816(acc[2 * pp], aL, bH[0], bH[1]);
                    mma16816(acc[2 * pp + 1], aH, bH[2], bH[3]);
                    mma16816(acc[2 * pp + 1], aH, bL[2], bL[3]);
                    mma16816(acc[2 * pp + 1], aL, bH[2], bH[3]);
                }
            }
            #pragma unroll
            for (int nb = 0; nb < 8; nb++) {
                int c = nhf * 64 + nb * 8 + 2 * t;
                float bb0 = s_b1[c], bb1 = s_b1[c + 1];
                int rA = R0 + g, rB = rA + 8;
                int w = nb * 4 + t;
                float h00 = fmaxf(acc[nb][0] + bb0, 0.f);
                float h01 = fmaxf(acc[nb][1] + bb1, 0.f);
                float h10 = fmaxf(acc[nb][2] + bb0, 0.f);
                float h11 = fmaxf(acc[nb][3] + bb1, 0.f);
                uint32_t lo;
                uint32_t hi = pack2_split_hi(h00, h01, lo);
                *(uint32_t*)(smem + OF_HT + nhf * 16384 + SWZ_W(rA, w)) = hi;
                *(uint32_t*)(smem + OF_HT + 32768 + nhf * 16384 + SWZ_W(rA, w)) = lo;
                hi = pack2_split_hi(h10, h11, lo);
                *(uint32_t*)(smem + OF_HT + nhf * 16384 + SWZ_W(rB, w)) = hi;
                *(uint32_t*)(smem + OF_HT + 32768 + nhf * 16384 + SWZ_W(rB, w)) = lo;
            }
        }
        __syncthreads();   // B

        // -------- P2: enc2 MMA: z = h @ W2 + b2 -> ZB, + per-row ||z||^2 --------
        {
            const int a_row2 = rbw * 16 + a_roff;
            float acc2[4][4];
            #pragma unroll
            for (int nb = 0; nb < 4; nb++)
                #pragma unroll
                for (int u = 0; u < 4; u++) acc2[nb][u] = 0.f;

            #pragma unroll
            for (int khalf = 0; khalf < 2; khalf++) {
                #pragma unroll
                for (int kk = 0; kk < 4; kk++) {
                    uint32_t aH[4], aL[4];
                    uint32_t offA = SWZ_C(a_row2, 2 * kk + a_ch);
                    ldsm_x4(aH, smb + OF_HT + khalf * 16384 + offA);
                    ldsm_x4(aL, smb + OF_HT + 32768 + khalf * 16384 + offA);
                    #pragma unroll
                    for (int pp = 0; pp < 2; pp++) {
                        int nrow = nhf * 32 + pp * 16 + b_row0;
                        uint32_t offB = SWZ_C(nrow, 2 * kk + b_ch);
                        uint32_t bH[4], bL[4];
                        ldsm_x4(bH, smb + OF_W2 + khalf * 8192 + offB);
                        ldsm_x4(bL, smb + OF_W2 + 16384 + khalf * 8192 + offB);
                        mma16816(acc2[2 * pp], aH, bH[0], bH[1]);
                        mma16816(acc2[2 * pp], aH, bL[0], bL[1]);
                        mma16816(acc2[2 * pp], aL, bH[0], bH[1]);
                        mma16816(acc2[2 * pp + 1], aH, bH[2], bH[3]);
                        mma16816(acc2[2 * pp + 1], aH, bL[2], bL[3]);
                        mma16816(acc2[2 * pp + 1], aL, bH[2], bH[3]);
                    }
                }
            }
            float z2A = 0.f, z2B = 0.f;
            int rA = rbw * 16 + g, rB = rA + 8;
            #pragma unroll
            for (int nb = 0; nb < 4; nb++) {
                int c0 = nhf * 32 + nb * 8 + 2 * t;
                int w = c0 >> 1;
                float bb0 = s_b2[c0], bb1 = s_b2[c0 + 1];
                float z00 = acc2[nb][0] + bb0, z01 = acc2[nb][1] + bb1;
                float z10 = acc2[nb][2] + bb0, z11 = acc2[nb][3] + bb1;
                z2A = fmaf(z00, z00, fmaf(z01, z01, z2A));
                z2B = fmaf(z10, z10, fmaf(z11, z11, z2B));
                uint32_t lo;
                uint32_t hi = pack2_split_hi(z00, z01, lo);
                *(uint32_t*)(smem + OF_ZBH + SWZ_W(rA, w)) = hi;
                *(uint32_t*)(smem + OF_ZBL + SWZ_W(rA, w)) = lo;
                hi = pack2_split_hi(z10, z11, lo);
                *(uint32_t*)(smem + OF_ZBH + SWZ_W(rB, w)) = hi;
                *(uint32_t*)(smem + OF_ZBL + SWZ_W(rB, w)) = lo;
            }
            #pragma unroll
            for (int off = 1; off <= 2; off <<= 1) {
                z2A += __shfl_xor_sync(0xffffffffu, z2A, off);
                z2B += __shfl_xor_sync(0xffffffffu, z2B, off);
            }
            if (t == 0) {
                s_z2[rA * 2 + nhf] = z2A;
                s_z2[rB * 2 + nhf] = z2B;
            }
        }
        __syncthreads();   // C

        // -------- P3: distance MMA over row-blocks; warp owns 32 codes --------
        #pragma unroll 1
        for (int rb = 0; rb < 8; rb++) {
            const int R0 = rb * 16;
            const int a_row3 = R0 + a_roff;
            uint32_t afH[4][4], afL[4][4];
            #pragma unroll
            for (int kk = 0; kk < 4; kk++) {
                uint32_t off = SWZ_C(a_row3, 2 * kk + a_ch);
                ldsm_x4(afH[kk], smb + OF_ZBH + off);
                ldsm_x4(afL[kk], smb + OF_ZBL + off);
            }
            float acc3[4][4];
            #pragma unroll
            for (int nb = 0; nb < 4; nb++)
                #pragma unroll
                for (int u = 0; u < 4; u++) acc3[nb][u] = 0.f;

            #pragma unroll
            for (int kk = 0; kk < 4; kk++) {
                #pragma unroll
                for (int pp = 0; pp < 2; pp++) {
                    uint32_t bL[4];
                    ldsm_x4(bL, smb + OF_CBL + SWZ_C(warp * 32 + pp * 16 + b_row0, 2 * kk + b_ch));
                    mma16816(acc3[2 * pp],     afH[kk], bL[0], bL[1]);   // zH*eL
                    mma16816(acc3[2 * pp + 1], afH[kk], bL[2], bL[3]);
                }
                #pragma unroll
                for (int nb = 0; nb < 4; nb++) {
                    mma16816(acc3[nb], afH[kk], bregH[nb][kk][0], bregH[nb][kk][1]);  // zH*eH
                    mma16816(acc3[nb], afL[kk], bregH[nb][kk][0], bregH[nb][kk][1]);  // zL*eH
                }
            }
            float mA = 3.4e38f, mB = 3.4e38f; int iA = 0, iB = 0;
            #pragma unroll
            for (int nb = 0; nb < 4; nb++) {
                int c0 = warp * 32 + nb * 8 + 2 * t;
                float e0 = s_e2[c0], e1 = s_e2[c0 + 1];
                float d00 = fmaf(-2.f, acc3[nb][0], e0);
                float d01 = fmaf(-2.f, acc3[nb][1], e1);
                float d10 = fmaf(-2.f, acc3[nb][2], e0);
                float d11 = fmaf(-2.f, acc3[nb][3], e1);
                if (d00 < mA) { mA = d00; iA = c0; }
                if (d01 < mA) { mA = d01; iA = c0 + 1; }
                if (d10 < mB) { mB = d10; iB = c0; }
                if (d11 < mB) { mB = d11; iB = c0 + 1; }
            }
            #pragma unroll
            for (int off = 1; off <= 2; off <<= 1) {
                float ov = __shfl_xor_sync(0xffffffffu, mA, off);
                int   oi = __shfl_xor_sync(0xffffffffu, iA, off);
                if (ov < mA || (ov == mA && oi < iA)) { mA = ov; iA = oi; }
                ov = __shfl_xor_sync(0xffffffffu, mB, off);
                oi = __shfl_xor_sync(0xffffffffu, iB, off);
                if (ov < mB || (ov == mB && oi < iB)) { mB = ov; iB = oi; }
            }
            if (t == 0) {
                atomicMin(&s_cand[R0 + g], dist_key(mA, iA));
                atomicMin(&s_cand[R0 + 8 + g], dist_key(mB, iB));
            }
        }
        __syncthreads();   // D

        // -------- P4: idx + vq = d_min + ||z||^2; reset cand --------
        if (tid < TILE_M) {
            unsigned long long key = s_cand[tid];
            g_idx[tle * TILE_M + tid] = (int)(key & 0xFFFFFFFFu);
            s_cand[tid] = ~0ULL;
            vq_local += dist_unkey(key) + s_z2[2 * tid] + s_z2[2 * tid + 1];
        }
        // no sync needed: next P0 writes only XB(=ZB) region
    }

    // ---- reduce vq ----
    #pragma unroll
    for (int off = 16; off; off >>= 1) vq_local += __shfl_down_sync(0xffffffffu, vq_local, off);
    __syncthreads();
    float* s_red = (float*)(smem + OF_CAND);
    if (lane == 0) s_red[warp] = vq_local;
    __syncthreads();
    if (tid == 0) {
        float s = 0.f;
        for (int w = 0; w < EWARPS; w++) s += s_red[w];
        g_vq_part[blockIdx.x] = s;
    }
}

// ============================================================================
// decoder table for 512 codes (exact fp32)
// ============================================================================
__global__ void k_hd(const float* __restrict__ cb,
                     const float* __restrict__ dw1, const float* __restrict__ db1)
{
    int gid = blockIdx.x * blockDim.x + threadIdx.x;
    int c = gid >> 7, j = gid & 127;
    float acc = db1[j];
    const float* q = cb + c * LAT;
    #pragma unroll 8
    for (int k = 0; k < LAT; k++) acc = fmaf(q[k], dw1[k * HID + j], acc);
    g_hd[gid] = fmaxf(acc, 0.f);
}

__global__ void k_tbl(const float* __restrict__ dw2, const float* __restrict__ db2)
{
    int gid = blockIdx.x * blockDim.x + threadIdx.x;
    int c = gid / IN_DIM, j = gid - c * IN_DIM;
    float acc = db2[j];
    const float* hd = g_hd + c * HID;
    #pragma unroll 8
    for (int k = 0; k < HID; k++) acc = fmaf(hd[k], dw2[k * IN_DIM + j], acc);
    g_tbl[gid] = acc;
}

// ============================================================================
// k_out: gather recon from table, write out, recon-loss partials
// ============================================================================
#define OUT_THREADS 512
__global__ void __launch_bounds__(OUT_THREADS)
k_out(const float* __restrict__ x, float* __restrict__ out)
{
    const int total4 = B_TOTAL * (IN_DIM / 4);          // 7 float4 per row
    const float4* x4 = (const float4*)x;
    float4* o4 = (float4*)out;
    const float4* t4 = (const float4*)g_tbl;

    float rec = 0.f;
    for (int f4 = blockIdx.x * OUT_THREADS + threadIdx.x; f4 < total4;
         f4 += KOUT_GRID * OUT_THREADS) {
        int row = f4 / 7;
        int w = f4 - row * 7;
        int idx = g_idx[row];
        float4 tv = t4[idx * 7 + w];
        float4 xv = x4[f4];
        o4[f4] = tv;
        float d0 = tv.x - xv.x, d1 = tv.y - xv.y, d2 = tv.z - xv.z, d3 = tv.w - xv.w;
        rec = fmaf(d0, d0, fmaf(d1, d1, fmaf(d2, d2, fmaf(d3, d3, rec))));
    }
    __shared__ float s_red[OUT_THREADS / 32];
    #pragma unroll
    for (int off = 16; off; off >>= 1) rec += __shfl_down_sync(0xffffffffu, rec, off);
    if ((threadIdx.x & 31) == 0) s_red[threadIdx.x >> 5] = rec;
    __syncthreads();
    if (threadIdx.x == 0) {
        float s = 0.f;
        for (int w = 0; w < OUT_THREADS / 32; w++) s += s_red[w];
        g_rec_part[blockIdx.x] = s;
    }
}

// ============================================================================
// finalize scalar losses
// ============================================================================
__global__ void k_final(float* __restrict__ out)
{
    if (threadIdx.x == 0) {
        double vs = 0.0, rs = 0.0;
        for (int i = 0; i < GRID1; i++) vs += (double)g_vq_part[i];
        for (int i = 0; i < KOUT_GRID; i++) rs += (double)g_rec_part[i];
        out[(long)B_TOTAL * IN_DIM]     = (float)(rs / ((double)B_TOTAL * IN_DIM));
        out[(long)B_TOTAL * IN_DIM + 1] = (float)(1.25 * vs / ((double)B_TOTAL * LAT));
    }
}

// ============================================================================
extern "C" void kernel_launch(void* const* d_in, const int* in_sizes, int n_in,
                              void* d_out, int out_size)
{
    const float* x    = (const float*)d_in[0];
    const float* ew1  = (const float*)d_in[1];
    const float* eb1  = (const float*)d_in[2];
    const float* ew2  = (const float*)d_in[3];
    const float* eb2  = (const float*)d_in[4];
    const float* cb   = (const float*)d_in[5];
    const float* dw1  = (const float*)d_in[6];
    const float* db1  = (const float*)d_in[7];
    const float* dw2  = (const float*)d_in[8];
    const float* db2  = (const float*)d_in[9];
    float* out = (float*)d_out;

    cudaFuncSetAttribute(k_encode, cudaFuncAttributeMaxDynamicSharedMemorySize, SMEM_E);

    k_hd<<<(NCODES * HID) / 256, 256>>>(cb, dw1, db1);
    k_tbl<<<(NCODES * IN_DIM) / 256, 256>>>(dw2, db2);
    k_encode<<<GRID1, ETHREADS, SMEM_E>>>(x, ew1, eb1, ew2, eb2, cb);
    k_out<<<KOUT_GRID, OUT_THREADS>>>(x, out);
    k_final<<<1, 32>>>(out);
}